// round 16
// baseline (speedup 1.0000x reference)
#include <cuda_runtime.h>
#include <cuda_bf16.h>
#include <cuda_fp16.h>
#include <cstdint>

// Problem constants (fixed by the dataset)
#define BATCH 2
#define SEQ   2048
#define DMODEL 1024
#define NHEAD 16
#define DHEAD 64
#define QKVDIM (3 * NHEAD * DHEAD)   // 3072
#define ROWS  (BATCH * SEQ)          // 4096

#define QSCALE (0.125f * 1.44269504088896340736f)   // 1/sqrt(64) * log2(e)

// Scratch (allocation-free rule: __device__ globals)
__device__ __half g_Wh[(size_t)QKVDIM * DMODEL];    // Wqkv^T fp16
__device__ __half g_Wp[(size_t)DMODEL * DMODEL];    // Wproj^T fp16
__device__ __half g_Xh[(size_t)ROWS * DMODEL];      // hidden, fp16
__device__ __half g_Oh[(size_t)ROWS * DMODEL];      // attention out, fp16
__device__ __half g_Q [(size_t)ROWS * DMODEL];      // q, fp16, pre-scaled
__device__ __half g_Kh[(size_t)ROWS * DMODEL];      // k fp16
__device__ __half g_Vh[(size_t)ROWS * DMODEL];      // v fp16

// ===========================================================================
// Helpers
// ===========================================================================
__device__ __forceinline__ uint32_t smem_u32(const void* p) {
    uint32_t a;
    asm("{ .reg .u64 t; cvta.to.shared.u64 t, %1; cvt.u32.u64 %0, t; }"
        : "=r"(a) : "l"(p));
    return a;
}

__device__ __forceinline__ void cp_async16(uint32_t dst, const void* src) {
    asm volatile("cp.async.cg.shared.global [%0], [%1], 16;"
                 :: "r"(dst), "l"(src) : "memory");
}
__device__ __forceinline__ void cp_commit() {
    asm volatile("cp.async.commit_group;" ::: "memory");
}
template <int N>
__device__ __forceinline__ void cp_wait() {
    asm volatile("cp.async.wait_group %0;" :: "n"(N) : "memory");
}

__device__ __forceinline__ void ldsm_x4(uint32_t& r0, uint32_t& r1,
                                        uint32_t& r2, uint32_t& r3,
                                        uint32_t addr) {
    asm volatile("ldmatrix.sync.aligned.m8n8.x4.shared.b16 {%0,%1,%2,%3}, [%4];"
                 : "=r"(r0), "=r"(r1), "=r"(r2), "=r"(r3) : "r"(addr));
}

__device__ __forceinline__ void ldsm_x4_t(uint32_t& r0, uint32_t& r1,
                                          uint32_t& r2, uint32_t& r3,
                                          uint32_t addr) {
    asm volatile("ldmatrix.sync.aligned.m8n8.x4.trans.shared.b16 {%0,%1,%2,%3}, [%4];"
                 : "=r"(r0), "=r"(r1), "=r"(r2), "=r"(r3) : "r"(addr));
}

__device__ __forceinline__ void mma_f16(float& c0, float& c1, float& c2, float& c3,
                                        uint32_t a0, uint32_t a1, uint32_t a2, uint32_t a3,
                                        uint32_t b0, uint32_t b1) {
    asm volatile(
        "mma.sync.aligned.m16n8k16.row.col.f32.f16.f16.f32 "
        "{%0,%1,%2,%3}, {%4,%5,%6,%7}, {%8,%9}, {%0,%1,%2,%3};"
        : "+f"(c0), "+f"(c1), "+f"(c2), "+f"(c3)
        : "r"(a0), "r"(a1), "r"(a2), "r"(a3), "r"(b0), "r"(b1));
}

__device__ __forceinline__ float ex2f(float x) {
    float y;
    asm("ex2.approx.f32 %0, %1;" : "=f"(y) : "f"(x));
    return y;
}

__device__ __forceinline__ uint32_t pack_h2(float lo, float hi) {
    uint32_t d;
    asm("cvt.rn.f16x2.f32 %0, %1, %2;" : "=r"(d) : "f"(hi), "f"(lo));
    return d;
}
__device__ __forceinline__ float2 unpack_h2(uint32_t u) {
    __half2 hh = *reinterpret_cast<__half2*>(&u);
    return __half22float2(hh);
}

// 128B-row swizzled tile offset (row-stride 128B, 16B segs, xor phase r&7)
__device__ __forceinline__ uint32_t t128_off(int r, int c) {
    return (uint32_t)(r * 128 + ((((c >> 3) ^ (r & 7)) & 7) * 16) + ((c & 7) * 2));
}

// ===========================================================================
// Fused pre-processing: one launch.
// ===========================================================================
#define PREP_CONV_BLKS 4096
#define PREP_TQKV_BLKS 3072
#define PREP_BLKS (PREP_CONV_BLKS + PREP_TQKV_BLKS + 1024)

__global__ __launch_bounds__(256) void prep_all(
    const float* __restrict__ hidden, const float* __restrict__ Wqkv,
    const float* __restrict__ Wproj,
    __half* __restrict__ Xh, __half* __restrict__ Wh, __half* __restrict__ Wp)
{
    __shared__ float t[32][33];
    const int bid = blockIdx.x;
    const int tid = threadIdx.x;

    if (bid < PREP_CONV_BLKS) {
        const int i = bid * 256 + tid;
        float4 v = ((const float4*)hidden)[i];
        uint2 hh;
        hh.x = pack_h2(v.x, v.y);
        hh.y = pack_h2(v.z, v.w);
        *(uint2*)(Xh + (size_t)i * 4) = hh;
        return;
    }

    const float* in;
    __half* outp;
    int K, N, tb;
    if (bid < PREP_CONV_BLKS + PREP_TQKV_BLKS) {
        tb = bid - PREP_CONV_BLKS;
        in = Wqkv; outp = Wh; K = DMODEL; N = QKVDIM;
    } else {
        tb = bid - PREP_CONV_BLKS - PREP_TQKV_BLKS;
        in = Wproj; outp = Wp; K = DMODEL; N = DMODEL;
    }
    const int ntiles_x = N / 32;
    const int nb = (tb % ntiles_x) * 32;
    const int kb = (tb / ntiles_x) * 32;
    const int x = tid & 31;
    const int y = tid >> 5;
    #pragma unroll
    for (int i = 0; i < 32; i += 8)
        t[y + i][x] = in[(size_t)(kb + y + i) * N + nb + x];
    __syncthreads();
    #pragma unroll
    for (int i = 0; i < 32; i += 8)
        outp[(size_t)(nb + y + i) * K + kb + x] = __float2half(t[x][y + i]);
}

// ===========================================================================
// fp16 tensor-core GEMM: C = A @ B^T + bias (single product)
// CTA tile 128x128, BK=64, 8 warps (4m x 2n), 3-stage cp.async pipeline
// (wait_group 1 in steady state), hoisted pointers + XOR-hoisted ldsm.
// ===========================================================================
#define GBM 128
#define GBN 128
#define GBK 64
#define SB_A  0
#define SB_B  16384
#define SB_BUF 32768
#define GEMM_SMEM (3 * SB_BUF)

__global__ __launch_bounds__(256, 2)
void gemm_f16k(const __half* __restrict__ A, const __half* __restrict__ B,
               const float* __restrict__ bias, float* __restrict__ C,
               int M, int N, int K, int mode,
               __half* __restrict__ Qo,
               __half* __restrict__ Kho, __half* __restrict__ Vho)
{
    extern __shared__ char smg[];
    const uint32_t smb = smem_u32(smg);

    const int tid  = threadIdx.x;
    const int wid  = tid >> 5;
    const int lane = tid & 31;
    const int wm   = wid & 3;
    const int wn   = wid >> 2;
    const int m0 = blockIdx.y * GBM;
    const int n0 = blockIdx.x * GBN;
    const int NCH = K / GBK;

    const int mat = lane >> 3;
    const int l7  = lane & 7;

    // ---- hoisted loader state ----
    const int lr0 = tid >> 3, lc0 = (tid & 7) * 8;
    const uint32_t loff0 = t128_off(lr0, lc0);
    const __half* Ap = A + (size_t)(m0 + lr0) * K + lc0;
    const __half* Bp = B + (size_t)(n0 + lr0) * K + lc0;
    const size_t K32 = (size_t)32 * K;

    auto load_chunk = [&](int b) {
        const uint32_t dst = smb + b * SB_BUF;
        #pragma unroll
        for (int t = 0; t < 4; t++) {
            const uint32_t off = loff0 + (uint32_t)(t * 4096);
            cp_async16(dst + SB_A + off, Ap + t * K32);
            cp_async16(dst + SB_B + off, Bp + t * K32);
        }
        cp_commit();
        Ap += GBK;
        Bp += GBK;
    };

    // ---- hoisted ldsm offsets ----
    uint32_t aoff[2], boff[4];
    #pragma unroll
    for (int mt = 0; mt < 2; mt++) {
        const int r = wm * 32 + mt * 16 + ((mat & 1) << 3) + l7;
        aoff[mt] = SB_A + t128_off(r, (mat >> 1) << 3);
    }
    #pragma unroll
    for (int p = 0; p < 4; p++) {
        const int r = wn * 64 + p * 16 + ((mat >> 1) << 3) + l7;
        boff[p] = SB_B + t128_off(r, (mat & 1) << 3);
    }

    float acc[2][8][4];
    #pragma unroll
    for (int mt = 0; mt < 2; mt++)
        #pragma unroll
        for (int nt = 0; nt < 8; nt++)
            #pragma unroll
            for (int j = 0; j < 4; j++)
                acc[mt][nt][j] = 0.0f;

    load_chunk(0);
    load_chunk(1);

    for (int c = 0; c < NCH; c++) {
        const int b = c % 3;
        if (c + 1 < NCH) { cp_wait<1>(); }
        else             { cp_wait<0>(); }
        __syncthreads();                   // stage b ready; stage (c-1)%3 free
        if (c + 2 < NCH) load_chunk((c + 2) % 3);

        const uint32_t base = smb + b * SB_BUF;

        #pragma unroll
        for (int ks = 0; ks < 4; ks++) {
            const uint32_t kx = (uint32_t)(ks << 5);

            uint32_t ah[2][4];
            #pragma unroll
            for (int mt = 0; mt < 2; mt++)
                ldsm_x4(ah[mt][0], ah[mt][1], ah[mt][2], ah[mt][3],
                        base + (aoff[mt] ^ kx));

            uint32_t bh[8][2];
            #pragma unroll
            for (int p = 0; p < 4; p++)
                ldsm_x4(bh[2*p][0], bh[2*p][1], bh[2*p+1][0], bh[2*p+1][1],
                        base + (boff[p] ^ kx));

            #pragma unroll
            for (int mt = 0; mt < 2; mt++)
                #pragma unroll
                for (int nt = 0; nt < 8; nt++)
                    mma_f16(acc[mt][nt][0], acc[mt][nt][1], acc[mt][nt][2], acc[mt][nt][3],
                            ah[mt][0], ah[mt][1], ah[mt][2], ah[mt][3],
                            bh[nt][0], bh[nt][1]);
        }
    }

    // Epilogue
    const int er = lane >> 2;
    const int ec = (lane & 3) * 2;
    if (mode == 0) {
        #pragma unroll
        for (int mt = 0; mt < 2; mt++) {
            #pragma unroll
            for (int nt = 0; nt < 8; nt++) {
                const int col = n0 + wn * 64 + nt * 8 + ec;
                const float b0 = bias[col], b1 = bias[col + 1];
                const int row0 = m0 + wm * 32 + mt * 16 + er;
                float2 v0 = make_float2(acc[mt][nt][0] + b0, acc[mt][nt][1] + b1);
                float2 v1 = make_float2(acc[mt][nt][2] + b0, acc[mt][nt][3] + b1);
                *(float2*)(C + (size_t)row0 * N + col)       = v0;
                *(float2*)(C + (size_t)(row0 + 8) * N + col) = v1;
            }
        }
    } else {
        const int sec = n0 >> 10;          // 0=Q, 1=K, 2=V
        __half* Ho = (sec == 1) ? Kho : Vho;
        #pragma unroll
        for (int mt = 0; mt < 2; mt++) {
            #pragma unroll
            for (int nt = 0; nt < 8; nt++) {
                const int col = n0 + wn * 64 + nt * 8 + ec;
                const int cloc = col & 1023;
                const float b0 = bias[col], b1 = bias[col + 1];
                const int row0 = m0 + wm * 32 + mt * 16 + er;
                const float x0 = acc[mt][nt][0] + b0, y0 = acc[mt][nt][1] + b1;
                const float x1 = acc[mt][nt][2] + b0, y1 = acc[mt][nt][3] + b1;
                if (sec == 0) {
                    *(uint32_t*)(Qo + (size_t)row0 * DMODEL + cloc)
                        = pack_h2(x0 * QSCALE, y0 * QSCALE);
                    *(uint32_t*)(Qo + (size_t)(row0 + 8) * DMODEL + cloc)
                        = pack_h2(x1 * QSCALE, y1 * QSCALE);
                } else {
                    *(uint32_t*)(Ho + (size_t)row0 * DMODEL + cloc) = pack_h2(x0, y0);
                    *(uint32_t*)(Ho + (size_t)(row0 + 8) * DMODEL + cloc) = pack_h2(x1, y1);
                }
            }
        }
    }
}

// ===========================================================================
// Tensor-core flash attention, 64-q-row CTAs, 2 CTAs/SM, split softmax,
// 3-stage cp.async K/V pipeline (wait_group 1 in steady state).
// smem: Q 8K | stage0..2 96K (K,V) | lred 256B | mred 256B
// ===========================================================================
#define ATT_Q    0
#define ATT_ST   8192
#define ATT_STG  32768
#define ST_KH    0
#define ST_VH    16384
#define ATT_LRED (ATT_ST + 3 * ATT_STG)     // 106496
#define ATT_MRED (ATT_LRED + 256)
#define ATT_SMEM (ATT_MRED + 256)           // 107008

__global__ __launch_bounds__(256, 2) void attn_mma(
    const __half* __restrict__ Qg,
    const __half* __restrict__ Kh,
    const __half* __restrict__ Vh,
    __half* __restrict__ Oh)
{
    extern __shared__ char sma[];
    const uint32_t smb = smem_u32(sma);
    float* lred = (float*)(sma + ATT_LRED);
    float* mred = (float*)(sma + ATT_MRED);

    const int bid = blockIdx.x;
    const int qt  = 31 - (bid >> 5);          // 64-row q tile, heavy first
    const int bh  = bid & 31;
    const int b   = bh >> 4;
    const int h   = bh & 15;
    const int kdmax = qt >> 1;                // last 128-key tile index

    const int tid  = threadIdx.x;
    const int wid  = tid >> 5;
    const int lane = tid & 31;
    const int wm   = wid & 3;                 // q rows wm*16
    const int wn   = wid >> 2;                // keys wn*64
    const int mat  = lane >> 3;
    const int l7   = lane & 7;
    const int er   = lane >> 2;
    const int ec   = (lane & 3) * 2;

    const size_t rowbase = (size_t)b * SEQ;

    // ---- hoisted prefetch state ----
    const int pr0 = tid >> 3, pg0 = tid & 7;
    const uint32_t psw0 = (uint32_t)(pr0 * 128) + (((pg0 ^ (pr0 & 7)) & 7) * 16);
    const __half* kp = Kh + (rowbase + pr0) * DMODEL + h * DHEAD + pg0 * 8;
    const __half* vp = Vh + (rowbase + pr0) * DMODEL + h * DHEAD + pg0 * 8;
    const size_t D32 = (size_t)32 * DMODEL;

    auto prefetch = [&](int st) {
        const uint32_t dst = smb + ATT_ST + st * ATT_STG;
        #pragma unroll
        for (int it = 0; it < 4; it++) {
            const uint32_t sw = psw0 + (uint32_t)(it * 4096);
            cp_async16(dst + ST_KH + sw, kp + it * D32);
            cp_async16(dst + ST_VH + sw, vp + it * D32);
        }
        cp_commit();
        kp += 4 * D32;
        vp += 4 * D32;
    };

    // ---- Load Q tile (64 rows) ----
    #pragma unroll
    for (int it = 0; it < 2; it++) {
        const int t = tid + it * 256;
        const int r = t >> 3, g = t & 7;
        const uint32_t sw = (uint32_t)(r * 128) + (((g ^ (r & 7)) & 7) * 16);
        uint4 v = *(const uint4*)(Qg + (rowbase + qt * 64 + r) * DMODEL + h * DHEAD + g * 8);
        *(uint4*)(sma + ATT_Q + sw) = v;
    }
    prefetch(0);
    if (kdmax >= 1) prefetch(1);
    __syncthreads();

    // ---- Q A-fragments (persistent) ----
    uint32_t qa[4][4];
    #pragma unroll
    for (int k16 = 0; k16 < 4; k16++) {
        const int r  = wm * 16 + ((mat & 1) << 3) + l7;
        const int kc = k16 * 16 + ((mat >> 1) << 3);
        ldsm_x4(qa[k16][0], qa[k16][1], qa[k16][2], qa[k16][3],
                smb + ATT_Q + t128_off(r, kc));
    }

    // ---- Hoisted ldsm base addresses (stage-relative) ----
    uint32_t koff[4];
    #pragma unroll
    for (int p = 0; p < 4; p++) {
        const int r = wn * 64 + p * 16 + ((mat >> 1) << 3) + l7;
        koff[p] = ST_KH + t128_off(r, (mat & 1) << 3);
    }
    const uint32_t voff0 = ST_VH +
        t128_off(wn * 64 + ((mat & 1) << 3) + l7, (mat >> 1) << 3);

    float mst[2], lst[2], oa[8][4];
    #pragma unroll
    for (int h2 = 0; h2 < 2; h2++) { mst[h2] = -1e30f; lst[h2] = 0.0f; }
    #pragma unroll
    for (int nt = 0; nt < 8; nt++)
        #pragma unroll
        for (int j = 0; j < 4; j++) oa[nt][j] = 0.0f;

    int st = 0;
    for (int kd = 0; kd <= kdmax; kd++) {
        if (kd < kdmax) { cp_wait<1>(); }
        else            { cp_wait<0>(); }
        __syncthreads();                       // stage st ready
        if (kd + 2 <= kdmax) prefetch((st + 2) % 3);

        const uint32_t stb = smb + ATT_ST + st * ATT_STG;
        st = (st + 1 == 3) ? 0 : st + 1;

        // ---- S = Q @ K^T (single product) ----
        float sc[8][4];
        #pragma unroll
        for (int nt = 0; nt < 8; nt++)
            #pragma unroll
            for (int j = 0; j < 4; j++) sc[nt][j] = 0.0f;

        #pragma unroll
        for (int k16 = 0; k16 < 4; k16++) {
            const uint32_t kx = (uint32_t)(k16 << 5);
            uint32_t bf[8][2];
            #pragma unroll
            for (int p = 0; p < 4; p++)
                ldsm_x4(bf[2*p][0], bf[2*p][1], bf[2*p+1][0], bf[2*p+1][1],
                        stb + (koff[p] ^ kx));
            #pragma unroll
            for (int nt = 0; nt < 8; nt++)
                mma_f16(sc[nt][0], sc[nt][1], sc[nt][2], sc[nt][3],
                        qa[k16][0], qa[k16][1], qa[k16][2], qa[k16][3],
                        bf[nt][0], bf[nt][1]);
        }

        // ---- Causal mask (diagonal tile only) ----
        if (kd == kdmax) {
            #pragma unroll
            for (int nt = 0; nt < 8; nt++)
                #pragma unroll
                for (int j = 0; j < 4; j++) {
                    const int grow = qt * 64 + wm * 16 + (j >> 1) * 8 + er;
                    const int gcol = kd * 128 + wn * 64 + nt * 8 + ec + (j & 1);
                    if (gcol > grow) sc[nt][j] = -1e30f;
                }
        }

        // ---- LOCAL row max (intra-warp only) ----
        float corr[2];
        #pragma unroll
        for (int h2 = 0; h2 < 2; h2++) {
            float mx = -1e30f;
            #pragma unroll
            for (int nt = 0; nt < 8; nt++) {
                mx = fmaxf(mx, sc[nt][2*h2]);
                mx = fmaxf(mx, sc[nt][2*h2+1]);
            }
            mx = fmaxf(mx, __shfl_xor_sync(0xffffffffu, mx, 1));
            mx = fmaxf(mx, __shfl_xor_sync(0xffffffffu, mx, 2));
            const float mnew = fmaxf(mst[h2], mx);
            corr[h2] = ex2f(mst[h2] - mnew);
            mst[h2] = mnew;
        }

        // ---- exp2 + local l ----
        {
            float psum[2] = {0.0f, 0.0f};
            #pragma unroll
            for (int nt = 0; nt < 8; nt++)
                #pragma unroll
                for (int j = 0; j < 4; j++) {
                    const int h2 = j >> 1;
                    const float pv = ex2f(sc[nt][j] - mst[h2]);
                    sc[nt][j] = pv;
                    psum[h2] += pv;
                }
            #pragma unroll
            for (int h2 = 0; h2 < 2; h2++) {
                float s = psum[h2];
                s += __shfl_xor_sync(0xffffffffu, s, 1);
                s += __shfl_xor_sync(0xffffffffu, s, 2);
                lst[h2] = lst[h2] * corr[h2] + s;
            }
            #pragma unroll
            for (int nt = 0; nt < 8; nt++)
                #pragma unroll
                for (int j = 0; j < 4; j++)
                    oa[nt][j] *= corr[j >> 1];
        }

        // ---- PV: P @ V (single product, fp16 P) ----
        #pragma unroll
        for (int kt2 = 0; kt2 < 4; kt2++) {
            uint32_t ah[4];
            #pragma unroll
            for (int q4 = 0; q4 < 4; q4++) {
                const int nt = 2 * kt2 + (q4 >> 1);
                const int j0 = (q4 & 1) * 2;
                ah[q4] = pack_h2(sc[nt][j0], sc[nt][j0 + 1]);
            }
            const uint32_t vb = stb + voff0 + (uint32_t)(kt2 * 2048);
            uint32_t bvh[8][2];
            #pragma unroll
            for (int ntp = 0; ntp < 4; ntp++)
                ldsm_x4_t(bvh[2*ntp][0], bvh[2*ntp][1], bvh[2*ntp+1][0], bvh[2*ntp+1][1],
                          vb ^ (uint32_t)(ntp << 5));
            #pragma unroll
            for (int nt = 0; nt < 8; nt++)
                mma_f16(oa[nt][0], oa[nt][1], oa[nt][2], oa[nt][3],
                        ah[0], ah[1], ah[2], ah[3], bvh[nt][0], bvh[nt][1]);
        }
    }

    // ---- Merge the two n-warp halves (scale by 2^(m_i - m)), write fp16 O --
    __syncthreads();
    float* ored = (float*)(sma + ATT_ST);     // 64 x 64 floats = 16KB
    if (wn == 1) {
        #pragma unroll
        for (int nt = 0; nt < 8; nt++)
            #pragma unroll
            for (int h2 = 0; h2 < 2; h2++) {
                const int row = wm * 16 + h2 * 8 + er;
                *(float2*)&ored[row * 64 + nt * 8 + ec] =
                    make_float2(oa[nt][2*h2], oa[nt][2*h2+1]);
            }
        if ((lane & 3) == 0) {
            #pragma unroll
            for (int h2 = 0; h2 < 2; h2++) {
                const int row = wm * 16 + h2 * 8 + er;
                lred[row] = lst[h2];
                mred[row] = mst[h2];
            }
        }
    }
    __syncthreads();
    if (wn == 0) {
        #pragma unroll
        for (int h2 = 0; h2 < 2; h2++) {
            const int row = wm * 16 + h2 * 8 + er;
            const float m1 = mred[row], l1 = lred[row];
            const float m  = fmaxf(mst[h2], m1);
            const float s0 = ex2f(mst[h2] - m);
            const float s1 = ex2f(m1 - m);
            const float inv = 1.0f / (lst[h2] * s0 + l1 * s1);
            const float f0 = s0 * inv, f1 = s1 * inv;
            const size_t go = (rowbase + qt * 64 + row) * DMODEL + h * DHEAD;
            #pragma unroll
            for (int nt = 0; nt < 8; nt++) {
                const float2 o2 = *(const float2*)&ored[row * 64 + nt * 8 + ec];
                const float wx = oa[nt][2*h2]     * f0 + o2.x * f1;
                const float wy = oa[nt][2*h2 + 1] * f0 + o2.y * f1;
                *(uint32_t*)(Oh + go + nt * 8 + ec) = pack_h2(wx, wy);
            }
        }
    }
}

// ===========================================================================
// kernel_launch
// ===========================================================================
extern "C" void kernel_launch(void* const* d_in, const int* in_sizes, int n_in,
                              void* d_out, int out_size)
{
    const float* hidden = (const float*)d_in[0];
    const float* Wqkv   = (const float*)d_in[2];
    const float* bqkv   = (const float*)d_in[3];
    const float* Wproj  = (const float*)d_in[4];
    const float* bproj  = (const float*)d_in[5];
    float* out = (float*)d_out;

    __half *Wh, *Wp, *Xh, *Oh, *Q, *Kh, *Vh;
    cudaGetSymbolAddress((void**)&Wh, g_Wh);
    cudaGetSymbolAddress((void**)&Wp, g_Wp);
    cudaGetSymbolAddress((void**)&Xh, g_Xh);
    cudaGetSymbolAddress((void**)&Oh, g_Oh);
    cudaGetSymbolAddress((void**)&Q,  g_Q);
    cudaGetSymbolAddress((void**)&Kh, g_Kh);
    cudaGetSymbolAddress((void**)&Vh, g_Vh);

    static bool attr_set = false;
    if (!attr_set) {
        cudaFuncSetAttribute(gemm_f16k, cudaFuncAttributeMaxDynamicSharedMemorySize,
                             GEMM_SMEM);
        cudaFuncSetAttribute(attn_mma, cudaFuncAttributeMaxDynamicSharedMemorySize,
                             ATT_SMEM);
        attr_set = true;
    }

    // ---- Fused prep: hidden->fp16, both weight transposes (one launch) ----
    prep_all<<<PREP_BLKS, 256>>>(hidden, Wqkv, Wproj, Xh, Wh, Wp);

    // ---- QKV projection (epilogue emits attention-native fp16 buffers) ----
    {
        dim3 grid(QKVDIM / GBN, ROWS / GBM);   // (24, 32)
        gemm_f16k<<<grid, 256, GEMM_SMEM>>>(Xh, Wh, bqkv, nullptr,
                                            ROWS, QKVDIM, DMODEL, 1,
                                            Q, Kh, Vh);
    }

    // ---- Flash causal attention (split softmax, writes fp16 O) ----
    attn_mma<<<1024, 256, ATT_SMEM>>>(Q, Kh, Vh, Oh);

    // ---- Output projection ----
    {
        dim3 grid(DMODEL / GBN, ROWS / GBM);   // (8, 32)
        gemm_f16k<<<grid, 256, GEMM_SMEM>>>(Oh, Wp, bproj, out,
                                            ROWS, DMODEL, DMODEL, 0,
                                            nullptr, nullptr, nullptr);
    }
}